// round 15
// baseline (speedup 1.0000x reference)
#include <cuda_runtime.h>

#define NP 400000
#define SXYZ 11264000
#define SYZ 16000
#define SZ 20
#define NWORDS 704000
#define SCAN_BLOCKS 688

#define OFF0 (0.05f)
#define OFF1 (0.05f - 40.0f)
#define OFF2 (0.1f - 3.0f)

__device__ unsigned g_bits[NWORDS];
__device__ unsigned g_wpre[NWORDS];
__device__ unsigned g_bsum[SCAN_BLOCKS];
__device__ unsigned g_boff[SCAN_BLOCKS];
__device__ int      g_nuniq;
__device__ int      g_nmulti;
__device__ int      g_mlist[NP];
__device__ int      g_keys[NP];
__device__ int      g_inv[NP];
__device__ int      g_cnt[NP];
__device__ float    g_sums[NP * 3];
__device__ unsigned g_xmaxu[(size_t)NP * 64];   /* only multi segs used */
__device__ float    g_corr[(size_t)NP * 128];   /* only multi rows used */
__device__ float    g_wsum[8192];               /* W1a + W1b */
__device__ double   g_mom[65];                  /* Sf[10], Sff[55] */
__device__ double   g_st[384];                  /* [128:256) sum1, [256:384) sumsq1 */
__device__ float    g_s0[64], g_t0[64], g_s1[128], g_t1[128];

__device__ __forceinline__ void coords_of(float x, float y, float z,
                                          int& cx, int& cy, int& cz) {
    cx = (int)floorf(__fmul_rn(x, 10.0f));
    cy = (int)floorf(__fmul_rn(__fadd_rn(y, 40.0f), 10.0f));
    cz = (int)floorf(__fmul_rn(__fadd_rn(z, 3.0f), 5.0f));
}
__device__ __forceinline__ unsigned utrans(float x) {
    unsigned u = __float_as_uint(x);
    return (u & 0x80000000u) ? ~u : (u | 0x80000000u);
}
__device__ __forceinline__ float uinv(unsigned u) {
    return __uint_as_float((u & 0x80000000u) ? (u & 0x7fffffffu) : ~u);
}
__device__ __forceinline__ float tf32f(float x) {
    unsigned r;
    asm("cvt.rna.tf32.f32 %0, %1;" : "=r"(r) : "f"(x));
    return __uint_as_float(r);
}
__device__ __forceinline__ void mma_tf32(float* d,
                                         unsigned a0, unsigned a1,
                                         unsigned a2, unsigned a3,
                                         unsigned b0, unsigned b1) {
    asm volatile(
        "mma.sync.aligned.m16n8k8.row.col.f32.tf32.tf32.f32 "
        "{%0,%1,%2,%3}, {%4,%5,%6,%7}, {%8,%9}, {%0,%1,%2,%3};"
        : "+f"(d[0]), "+f"(d[1]), "+f"(d[2]), "+f"(d[3])
        : "r"(a0), "r"(a1), "r"(a2), "r"(a3), "r"(b0), "r"(b1));
}

__device__ __forceinline__ void compute_feat(const float* __restrict__ pts,
                                             int i, float* f,
                                             int& seg, int& cnt) {
    float x = pts[i * 5 + 1], y = pts[i * 5 + 2], z = pts[i * 5 + 3];
    float inten = pts[i * 5 + 4];
    int cx, cy, cz;
    coords_of(x, y, z, cx, cy, cz);
    seg = g_inv[i];
    cnt = g_cnt[seg];
    float fc = fmaxf((float)cnt, 1.f);
    f[0] = x; f[1] = y; f[2] = z; f[3] = inten;
    f[4] = __fsub_rn(x, __fdiv_rn(g_sums[seg * 3 + 0], fc));
    f[5] = __fsub_rn(y, __fdiv_rn(g_sums[seg * 3 + 1], fc));
    f[6] = __fsub_rn(z, __fdiv_rn(g_sums[seg * 3 + 2], fc));
    f[7] = __fsub_rn(x, __fadd_rn(__fmul_rn((float)cx, 0.1f), OFF0));
    f[8] = __fsub_rn(y, __fadd_rn(__fmul_rn((float)cy, 0.1f), OFF1));
    f[9] = __fsub_rn(z, __fadd_rn(__fmul_rn((float)cz, 0.2f), OFF2));
}

__global__ void k_keys(const float* __restrict__ pts) {
    int i = blockIdx.x * 256 + threadIdx.x;
    if (i >= NP) return;
    float b = pts[i * 5 + 0];
    float x = pts[i * 5 + 1], y = pts[i * 5 + 2], z = pts[i * 5 + 3];
    int cx, cy, cz;
    coords_of(x, y, z, cx, cy, cz);
    int key = (int)b * SXYZ + cx * SYZ + cy * SZ + cz;
    g_keys[i] = key;
    atomicOr(&g_bits[(unsigned)key >> 5], 1u << (key & 31));
}

__global__ void k_scan_words() {
    __shared__ unsigned sh[256];
    unsigned b = blockIdx.x, t = threadIdx.x;
    unsigned base = b * 1024u + t * 4u;
    uint4 w = make_uint4(0u, 0u, 0u, 0u);
    if (base < NWORDS) w = *(const uint4*)&g_bits[base];
    unsigned c0 = __popc(w.x), c1 = __popc(w.y), c2 = __popc(w.z), c3 = __popc(w.w);
    unsigned tot = c0 + c1 + c2 + c3;
    sh[t] = tot;
    __syncthreads();
    for (int off = 1; off < 256; off <<= 1) {
        unsigned v = (t >= (unsigned)off) ? sh[t - off] : 0u;
        __syncthreads();
        sh[t] += v;
        __syncthreads();
    }
    unsigned excl = sh[t] - tot;
    if (base < NWORDS) {
        g_wpre[base + 0] = excl;
        g_wpre[base + 1] = excl + c0;
        g_wpre[base + 2] = excl + c0 + c1;
        g_wpre[base + 3] = excl + c0 + c1 + c2;
    }
    if (t == 255) g_bsum[b] = sh[255];
}

__global__ void k_scan_blocks() {
    __shared__ unsigned sh[1024];
    int t = threadIdx.x;
    unsigned v = (t < SCAN_BLOCKS) ? g_bsum[t] : 0u;
    sh[t] = v;
    __syncthreads();
    for (int off = 1; off < 1024; off <<= 1) {
        unsigned u = (t >= off) ? sh[t - off] : 0u;
        __syncthreads();
        sh[t] += u;
        __syncthreads();
    }
    if (t < SCAN_BLOCKS) g_boff[t] = sh[t] - v;
    if (t == 1023) g_nuniq = (int)sh[1023];
}

__global__ void k_inv(const float* __restrict__ pts) {
    int i = blockIdx.x * 256 + threadIdx.x;
    if (i >= NP) return;
    int key = g_keys[i];
    unsigned w = (unsigned)key >> 5, bit = key & 31;
    unsigned rank = g_boff[w >> 10] + g_wpre[w] +
                    __popc(g_bits[w] & ((1u << bit) - 1u));
    g_inv[i] = (int)rank;
    atomicAdd(&g_cnt[rank], 1);
    atomicAdd(&g_sums[rank * 3 + 0], pts[i * 5 + 1]);
    atomicAdd(&g_sums[rank * 3 + 1], pts[i * 5 + 2]);
    atomicAdd(&g_sums[rank * 3 + 2], pts[i * 5 + 3]);
}

__global__ void k_zero(float* __restrict__ out, float* __restrict__ oc,
                       int emit_coords) {
    int i = blockIdx.x * 256 + threadIdx.x;
    if (i >= NP) return;
    int nu = g_nuniq;
    bool tail = i >= nu;
    bool multi = !tail && (g_cnt[i] > 1);
    if (tail || multi) {
        float4* o = (float4*)&out[(size_t)i * 128];
        #pragma unroll
        for (int q = 0; q < 32; q++) o[q] = make_float4(0.f, 0.f, 0.f, 0.f);
    }
    if (multi) {
        uint4* xm = (uint4*)&g_xmaxu[(size_t)i * 64];
        #pragma unroll
        for (int q = 0; q < 16; q++) xm[q] = make_uint4(0u, 0u, 0u, 0u);
    }
    if (tail && emit_coords)
        ((float4*)oc)[i] = make_float4(-1.f, 19.f, 799.f, 703.f);
}

__global__ void k_coords(float* __restrict__ oc) {
    int w = blockIdx.x * 256 + threadIdx.x;
    if (w >= NWORDS) return;
    unsigned m = g_bits[w];
    if (!m) return;
    unsigned r = g_boff[w >> 10] + g_wpre[w];
    int kb = w << 5;
    while (m) {
        int b = __ffs(m) - 1;
        m &= m - 1;
        int key = kb + b;
        int B = key / SXYZ;
        int rem = key % SXYZ;
        int X = rem / SYZ; rem -= X * SYZ;
        int Y = rem / SZ;
        int Z = rem - Y * SZ;
        ((float4*)oc)[r] = make_float4((float)B, (float)Z, (float)Y, (float)X);
        r++;
    }
}

__global__ void k_wsum(const float* __restrict__ W1) {
    int j = blockIdx.x * 256 + threadIdx.x;
    if (j < 8192) g_wsum[j] = W1[j] + W1[j + 8192];
}

__global__ void __launch_bounds__(256) k_prep(const float* __restrict__ pts,
                                              const float* __restrict__ W0) {
    __shared__ float w0s[640];
    __shared__ float sm[65];
    int tid = threadIdx.x;
    for (int j = tid; j < 640; j += 256) w0s[j] = W0[j];
    if (tid < 65) sm[tid] = 0.f;
    __syncthreads();
    float mom[65];
    #pragma unroll
    for (int v = 0; v < 65; v++) mom[v] = 0.f;
    int base = blockIdx.x * 2048;
    for (int i = base + tid; i < base + 2048 && i < NP; i += 256) {
        float f[10];
        int seg, cnt;
        compute_feat(pts, i, f, seg, cnt);
        #pragma unroll
        for (int k = 0; k < 10; k++) mom[k] += f[k];
        {
            int idx = 10;
            #pragma unroll
            for (int k = 0; k < 10; k++)
                #pragma unroll
                for (int l = k; l < 10; l++)
                    mom[idx++] += f[k] * f[l];
        }
        if (cnt > 1) {
            int mi = atomicAdd(&g_nmulti, 1);
            g_mlist[mi] = i;
            unsigned* xm = &g_xmaxu[(size_t)seg * 64];
            #pragma unroll 8
            for (int c = 0; c < 64; c++) {
                float acc = 0.f;
                #pragma unroll
                for (int k = 0; k < 10; k++) acc = fmaf(f[k], w0s[k * 64 + c], acc);
                atomicMax(&xm[c], utrans(acc));
            }
        }
    }
    int lane = tid & 31;
    #pragma unroll
    for (int v = 0; v < 65; v++) {
        float s = mom[v];
        #pragma unroll
        for (int o = 16; o; o >>= 1) s += __shfl_down_sync(0xffffffffu, s, o);
        if (lane == 0) atomicAdd(&sm[v], s);
    }
    __syncthreads();
    if (tid < 65) atomicAdd(&g_mom[tid], (double)sm[tid]);
}

__global__ void k_bn0(const float* __restrict__ W0,
                      const float* __restrict__ g, const float* __restrict__ b) {
    int c = threadIdx.x;
    if (c >= 64) return;
    double w[10];
    #pragma unroll
    for (int k = 0; k < 10; k++) w[k] = (double)W0[k * 64 + c];
    double mean = 0.0;
    #pragma unroll
    for (int k = 0; k < 10; k++) mean += w[k] * g_mom[k];
    mean /= (double)NP;
    double ey2 = 0.0;
    int idx = 10;
    #pragma unroll
    for (int k = 0; k < 10; k++)
        #pragma unroll
        for (int l = k; l < 10; l++) {
            double t = w[k] * w[l] * g_mom[idx++];
            ey2 += (k == l) ? t : 2.0 * t;
        }
    ey2 /= (double)NP;
    double var = ey2 - mean * mean;
    double s = (double)g[c] / sqrt(var + 0.001);
    g_s0[c] = (float)s;
    g_t0[c] = (float)((double)b[c] - mean * s);
}

/* shared prologue: fill tf32-rounded xs (h0, [k][m] stride 136) and ws
   ([k][n] stride 136) for one 128-point tile. */
__device__ __forceinline__ void fill_tile(const float* __restrict__ pts,
                                          const float* __restrict__ w0s,
                                          const float* __restrict__ sS,
                                          const float* __restrict__ sT,
                                          float* xs, float* ws,
                                          int bs, int tid) {
    for (int j = tid; j < 8192; j += 256) {
        int k = j >> 7, n = j & 127;
        ws[k * 136 + n] = tf32f(g_wsum[j]);
    }
    int m = tid & 127, half = tid >> 7;
    float f[10];
    int seg, cnt;
    compute_feat(pts, bs + m, f, seg, cnt);
    int cbase = half * 32;
    #pragma unroll 8
    for (int c = cbase; c < cbase + 32; c++) {
        float acc = 0.f;
        #pragma unroll
        for (int k = 0; k < 10; k++) acc = fmaf(f[k], w0s[k * 64 + c], acc);
        xs[c * 136 + m] = tf32f(fmaxf(fmaf(acc, sS[c], sT[c]), 0.f));
    }
}

/* shared mma core: D[16][4] = h0_tile(16 rows of warp) @ wsum (128 cols) */
__device__ __forceinline__ void mma_core(const float* xs, const float* ws,
                                         int m0, int gr, int tg,
                                         float D[16][4]) {
    const unsigned* xu = (const unsigned*)xs;
    const unsigned* wu = (const unsigned*)ws;
    #pragma unroll
    for (int kt = 0; kt < 8; kt++) {
        int k0 = kt * 8;
        unsigned a0 = xu[(k0 + tg) * 136 + m0 + gr];
        unsigned a1 = xu[(k0 + tg) * 136 + m0 + gr + 8];
        unsigned a2 = xu[(k0 + tg + 4) * 136 + m0 + gr];
        unsigned a3 = xu[(k0 + tg + 4) * 136 + m0 + gr + 8];
        #pragma unroll
        for (int nt = 0; nt < 16; nt++) {
            unsigned b0 = wu[(k0 + tg) * 136 + nt * 8 + gr];
            unsigned b1 = wu[(k0 + tg + 4) * 136 + nt * 8 + gr];
            mma_tf32(D[nt], a0, a1, a2, a3, b0, b1);
        }
    }
}

/* Pass 1: BN1 stats only (no y1 write) */
__global__ void __launch_bounds__(256, 2) k_gemm_stats(const float* __restrict__ pts,
                                                       const float* __restrict__ W0) {
    extern __shared__ float sh[];
    float* ws = sh;            /* 64*136 */
    float* xs = sh + 8704;     /* 64*136 */
    __shared__ float w0s[640];
    __shared__ float sS[64], sT[64];
    __shared__ float sa[128], sa2[128];
    int tid = threadIdx.x;
    if (tid < 64)  { sS[tid] = g_s0[tid]; sT[tid] = g_t0[tid]; }
    if (tid < 128) { sa[tid] = 0.f; sa2[tid] = 0.f; }
    for (int j = tid; j < 640; j += 256) w0s[j] = W0[j];
    __syncthreads();
    int bs = blockIdx.x * 128;
    fill_tile(pts, w0s, sS, sT, xs, ws, bs, tid);
    __syncthreads();

    int w = tid >> 5, lane = tid & 31, gr = lane >> 2, tg = lane & 3;
    int m0 = w * 16;
    float D[16][4];
    #pragma unroll
    for (int i = 0; i < 16; i++)
        #pragma unroll
        for (int j = 0; j < 4; j++) D[i][j] = 0.f;
    mma_core(xs, ws, m0, gr, tg, D);

    #pragma unroll
    for (int nt = 0; nt < 16; nt++) {
        int c0 = nt * 8 + 2 * tg;
        atomicAdd(&sa[c0],      D[nt][0] + D[nt][2]);
        atomicAdd(&sa[c0 + 1],  D[nt][1] + D[nt][3]);
        atomicAdd(&sa2[c0],     D[nt][0] * D[nt][0] + D[nt][2] * D[nt][2]);
        atomicAdd(&sa2[c0 + 1], D[nt][1] * D[nt][1] + D[nt][3] * D[nt][3]);
    }
    __syncthreads();
    if (tid < 128) {
        atomicAdd(&g_st[128 + tid], (double)sa[tid]);
        atomicAdd(&g_st[256 + tid], (double)sa2[tid]);
    }
}

/* multi-row correction: corr = (hmax - h0) @ W1b + stat deltas */
__global__ void k_corr(const float* __restrict__ pts,
                       const float* __restrict__ W0,
                       const float* __restrict__ W1) {
    __shared__ float w0s[640];
    __shared__ float hv[64], dv[64];
    int tid = threadIdx.x;   /* 128 */
    for (int j = tid; j < 640; j += 128) w0s[j] = W0[j];
    __syncthreads();
    double dsum = 0.0, dsq = 0.0;
    int nm = g_nmulti;
    for (int it = blockIdx.x; it < nm; it += gridDim.x) {
        int p = g_mlist[it];
        float f[10];
        int seg, cnt;
        compute_feat(pts, p, f, seg, cnt);
        if (tid < 64) {
            float acc = 0.f;
            #pragma unroll
            for (int k = 0; k < 10; k++) acc = fmaf(f[k], w0s[k * 64 + tid], acc);
            float h0 = fmaxf(fmaf(acc, g_s0[tid], g_t0[tid]), 0.f);
            float hm = fmaxf(fmaf(uinv(g_xmaxu[(size_t)seg * 64 + tid]),
                                  g_s0[tid], g_t0[tid]), 0.f);
            hv[tid] = tf32f(h0);
            dv[tid] = hm - h0;
        }
        __syncthreads();
        /* ya approximated with tf32-rounded h0 (matches mma operand rounding) */
        float ya = 0.f, co = 0.f;
        #pragma unroll 8
        for (int k = 0; k < 64; k++) ya = fmaf(hv[k], tf32f(g_wsum[k * 128 + tid]), ya);
        #pragma unroll 8
        for (int k = 0; k < 64; k++) co = fmaf(dv[k], W1[(64 + k) * 128 + tid], co);
        g_corr[(size_t)p * 128 + tid] = co;
        float nw = ya + co;
        dsum += (double)co;
        dsq  += (double)nw * (double)nw - (double)ya * (double)ya;
        __syncthreads();
    }
    atomicAdd(&g_st[128 + tid], dsum);
    atomicAdd(&g_st[256 + tid], dsq);
}

__global__ void k_bn1(const float* __restrict__ g, const float* __restrict__ b) {
    int c = threadIdx.x;
    if (c >= 128) return;
    double m = g_st[128 + c] / (double)NP;
    double var = g_st[256 + c] / (double)NP - m * m;
    double s = (double)g[c] / sqrt(var + 0.001);
    g_s1[c] = (float)s;
    g_t1[c] = (float)((double)b[c] - m * s);
}

/* Pass 2: recompute GEMM, add corr, BN1+relu+segment-max -> out */
__global__ void __launch_bounds__(256, 2) k_gemm_out(const float* __restrict__ pts,
                                                     const float* __restrict__ W0,
                                                     float* __restrict__ out) {
    extern __shared__ float sh[];
    float* ws = sh;
    float* xs = sh + 8704;
    __shared__ float w0s[640];
    __shared__ float sS[64], sT[64];
    __shared__ float ss1[128], st1[128];
    int tid = threadIdx.x;
    if (tid < 64)  { sS[tid] = g_s0[tid]; sT[tid] = g_t0[tid]; }
    if (tid < 128) { ss1[tid] = g_s1[tid]; st1[tid] = g_t1[tid]; }
    for (int j = tid; j < 640; j += 256) w0s[j] = W0[j];
    __syncthreads();
    int bs = blockIdx.x * 128;
    fill_tile(pts, w0s, sS, sT, xs, ws, bs, tid);
    __syncthreads();

    int w = tid >> 5, lane = tid & 31, gr = lane >> 2, tg = lane & 3;
    int m0 = w * 16;
    float D[16][4];
    #pragma unroll
    for (int i = 0; i < 16; i++)
        #pragma unroll
        for (int j = 0; j < 4; j++) D[i][j] = 0.f;
    mma_core(xs, ws, m0, gr, tg, D);

    int p1 = bs + m0 + gr, p2 = p1 + 8;
    int seg1 = g_inv[p1], seg2 = g_inv[p2];
    int cnt1 = g_cnt[seg1], cnt2 = g_cnt[seg2];
    const float* cr1 = &g_corr[(size_t)p1 * 128];
    const float* cr2 = &g_corr[(size_t)p2 * 128];
    float* o1 = &out[(size_t)seg1 * 128];
    float* o2 = &out[(size_t)seg2 * 128];
    #pragma unroll
    for (int nt = 0; nt < 16; nt++) {
        int c0 = nt * 8 + 2 * tg;
        float v0 = D[nt][0], v1 = D[nt][1], v2 = D[nt][2], v3 = D[nt][3];
        if (cnt1 > 1) { v0 += cr1[c0]; v1 += cr1[c0 + 1]; }
        if (cnt2 > 1) { v2 += cr2[c0]; v3 += cr2[c0 + 1]; }
        float h0 = fmaxf(fmaf(v0, ss1[c0],     st1[c0]),     0.f);
        float h1 = fmaxf(fmaf(v1, ss1[c0 + 1], st1[c0 + 1]), 0.f);
        float h2 = fmaxf(fmaf(v2, ss1[c0],     st1[c0]),     0.f);
        float h3 = fmaxf(fmaf(v3, ss1[c0 + 1], st1[c0 + 1]), 0.f);
        if (cnt1 == 1) {
            *(float2*)&o1[c0] = make_float2(h0, h1);
        } else {
            atomicMax((int*)&o1[c0],     __float_as_int(h0));
            atomicMax((int*)&o1[c0 + 1], __float_as_int(h1));
        }
        if (cnt2 == 1) {
            *(float2*)&o2[c0] = make_float2(h2, h3);
        } else {
            atomicMax((int*)&o2[c0],     __float_as_int(h2));
            atomicMax((int*)&o2[c0 + 1], __float_as_int(h3));
        }
    }
}

extern "C" void kernel_launch(void* const* d_in, const int* in_sizes, int n_in,
                              void* d_out, int out_size) {
    const float* pts = (const float*)d_in[0];
    const float* W0  = (const float*)d_in[1];
    const float* g0  = (const float*)d_in[2];
    const float* b0  = (const float*)d_in[3];
    const float* W1  = (const float*)d_in[4];
    const float* g1  = (const float*)d_in[5];
    const float* b1  = (const float*)d_in[6];
    float* out = (float*)d_out;
    float* oc = out + (size_t)NP * 128;
    int emit_coords = ((long long)out_size >= (long long)NP * 132);

    void *p_bits, *p_cnt, *p_sums, *p_st, *p_nm, *p_mom;
    cudaGetSymbolAddress(&p_bits, g_bits);
    cudaGetSymbolAddress(&p_cnt,  g_cnt);
    cudaGetSymbolAddress(&p_sums, g_sums);
    cudaGetSymbolAddress(&p_st,   g_st);
    cudaGetSymbolAddress(&p_nm,   g_nmulti);
    cudaGetSymbolAddress(&p_mom,  g_mom);

    cudaMemsetAsync(p_bits, 0, NWORDS * 4);
    cudaMemsetAsync(p_cnt,  0, NP * 4);
    cudaMemsetAsync(p_sums, 0, NP * 12);
    cudaMemsetAsync(p_st,   0, 384 * 8);
    cudaMemsetAsync(p_nm,   0, 4);
    cudaMemsetAsync(p_mom,  0, 65 * 8);

    k_keys<<<1563, 256>>>(pts);
    k_scan_words<<<SCAN_BLOCKS, 256>>>();
    k_scan_blocks<<<1, 1024>>>();
    k_inv<<<1563, 256>>>(pts);
    k_zero<<<1563, 256>>>(out, oc, emit_coords);
    if (emit_coords) {
        k_coords<<<2750, 256>>>(oc);
    }
    k_wsum<<<32, 256>>>(W1);
    k_prep<<<196, 256>>>(pts, W0);
    k_bn0<<<1, 64>>>(W0, g0, b0);
    cudaFuncSetAttribute(k_gemm_stats, cudaFuncAttributeMaxDynamicSharedMemorySize, 69632);
    cudaFuncSetAttribute(k_gemm_out,   cudaFuncAttributeMaxDynamicSharedMemorySize, 69632);
    k_gemm_stats<<<3125, 256, 69632>>>(pts, W0);
    k_corr<<<592, 128>>>(pts, W0, W1);
    k_bn1<<<1, 128>>>(g1, b1);
    k_gemm_out<<<3125, 256, 69632>>>(pts, W0, out);
}

// round 16
// speedup vs baseline: 1.4888x; 1.4888x over previous
#include <cuda_runtime.h>

#define NP 400000
#define SXYZ 11264000
#define SYZ 16000
#define SZ 20
#define NWORDS 704000
#define SCAN_BLOCKS 688

#define OFF0 (0.05f)
#define OFF1 (0.05f - 40.0f)
#define OFF2 (0.1f - 3.0f)

__device__ unsigned g_bits[NWORDS];
__device__ unsigned g_wpre[NWORDS];
__device__ unsigned g_bsum[SCAN_BLOCKS];
__device__ unsigned g_boff[SCAN_BLOCKS];
__device__ int      g_nuniq;
__device__ int      g_nmulti;
__device__ int      g_mlist[NP];
__device__ int      g_keys[NP];
__device__ int      g_inv[NP];
__device__ int      g_cnt[NP];
__device__ float    g_sums[NP * 3];
__device__ unsigned g_xmaxu[(size_t)NP * 64];   /* only multi segs used */
__device__ float    g_corr[(size_t)NP * 128];   /* only multi rows used */
__device__ float    g_wsum[8192];               /* W1a + W1b */
__device__ double   g_mom[65];                  /* Sf[10], Sff[55] */
__device__ double   g_st[384];                  /* [128:256) sum1, [256:384) sumsq1 */
__device__ float    g_s0[64], g_t0[64], g_s1[128], g_t1[128];

__device__ __forceinline__ void coords_of(float x, float y, float z,
                                          int& cx, int& cy, int& cz) {
    cx = (int)floorf(__fmul_rn(x, 10.0f));
    cy = (int)floorf(__fmul_rn(__fadd_rn(y, 40.0f), 10.0f));
    cz = (int)floorf(__fmul_rn(__fadd_rn(z, 3.0f), 5.0f));
}
__device__ __forceinline__ unsigned utrans(float x) {
    unsigned u = __float_as_uint(x);
    return (u & 0x80000000u) ? ~u : (u | 0x80000000u);
}
__device__ __forceinline__ float uinv(unsigned u) {
    return __uint_as_float((u & 0x80000000u) ? (u & 0x7fffffffu) : ~u);
}
__device__ __forceinline__ unsigned long long pk2(float a, float b) {
    unsigned long long r;
    asm("mov.b64 %0,{%1,%2};" : "=l"(r) : "f"(a), "f"(b));
    return r;
}
__device__ __forceinline__ void upk(unsigned long long v, float& a, float& b) {
    asm("mov.b64 {%0,%1},%2;" : "=f"(a), "=f"(b) : "l"(v));
}
__device__ __forceinline__ unsigned long long fma2(unsigned long long a,
                                                   unsigned long long b,
                                                   unsigned long long c) {
    unsigned long long d;
    asm("fma.rn.f32x2 %0,%1,%2,%3;" : "=l"(d) : "l"(a), "l"(b), "l"(c));
    return d;
}

__device__ __forceinline__ void compute_feat(const float* __restrict__ pts,
                                             int i, float* f,
                                             int& seg, int& cnt) {
    float x = pts[i * 5 + 1], y = pts[i * 5 + 2], z = pts[i * 5 + 3];
    float inten = pts[i * 5 + 4];
    int cx, cy, cz;
    coords_of(x, y, z, cx, cy, cz);
    seg = g_inv[i];
    cnt = g_cnt[seg];
    float fc = fmaxf((float)cnt, 1.f);
    f[0] = x; f[1] = y; f[2] = z; f[3] = inten;
    f[4] = __fsub_rn(x, __fdiv_rn(g_sums[seg * 3 + 0], fc));
    f[5] = __fsub_rn(y, __fdiv_rn(g_sums[seg * 3 + 1], fc));
    f[6] = __fsub_rn(z, __fdiv_rn(g_sums[seg * 3 + 2], fc));
    f[7] = __fsub_rn(x, __fadd_rn(__fmul_rn((float)cx, 0.1f), OFF0));
    f[8] = __fsub_rn(y, __fadd_rn(__fmul_rn((float)cy, 0.1f), OFF1));
    f[9] = __fsub_rn(z, __fadd_rn(__fmul_rn((float)cz, 0.2f), OFF2));
}

__global__ void k_keys(const float* __restrict__ pts) {
    int i = blockIdx.x * 256 + threadIdx.x;
    if (i >= NP) return;
    float b = pts[i * 5 + 0];
    float x = pts[i * 5 + 1], y = pts[i * 5 + 2], z = pts[i * 5 + 3];
    int cx, cy, cz;
    coords_of(x, y, z, cx, cy, cz);
    int key = (int)b * SXYZ + cx * SYZ + cy * SZ + cz;
    g_keys[i] = key;
    atomicOr(&g_bits[(unsigned)key >> 5], 1u << (key & 31));
}

__global__ void k_scan_words() {
    __shared__ unsigned sh[256];
    unsigned b = blockIdx.x, t = threadIdx.x;
    unsigned base = b * 1024u + t * 4u;
    uint4 w = make_uint4(0u, 0u, 0u, 0u);
    if (base < NWORDS) w = *(const uint4*)&g_bits[base];
    unsigned c0 = __popc(w.x), c1 = __popc(w.y), c2 = __popc(w.z), c3 = __popc(w.w);
    unsigned tot = c0 + c1 + c2 + c3;
    sh[t] = tot;
    __syncthreads();
    for (int off = 1; off < 256; off <<= 1) {
        unsigned v = (t >= (unsigned)off) ? sh[t - off] : 0u;
        __syncthreads();
        sh[t] += v;
        __syncthreads();
    }
    unsigned excl = sh[t] - tot;
    if (base < NWORDS) {
        g_wpre[base + 0] = excl;
        g_wpre[base + 1] = excl + c0;
        g_wpre[base + 2] = excl + c0 + c1;
        g_wpre[base + 3] = excl + c0 + c1 + c2;
    }
    if (t == 255) g_bsum[b] = sh[255];
}

__global__ void k_scan_blocks() {
    __shared__ unsigned sh[1024];
    int t = threadIdx.x;
    unsigned v = (t < SCAN_BLOCKS) ? g_bsum[t] : 0u;
    sh[t] = v;
    __syncthreads();
    for (int off = 1; off < 1024; off <<= 1) {
        unsigned u = (t >= off) ? sh[t - off] : 0u;
        __syncthreads();
        sh[t] += u;
        __syncthreads();
    }
    if (t < SCAN_BLOCKS) g_boff[t] = sh[t] - v;
    if (t == 1023) g_nuniq = (int)sh[1023];
}

__global__ void k_inv(const float* __restrict__ pts) {
    int i = blockIdx.x * 256 + threadIdx.x;
    if (i >= NP) return;
    int key = g_keys[i];
    unsigned w = (unsigned)key >> 5, bit = key & 31;
    unsigned rank = g_boff[w >> 10] + g_wpre[w] +
                    __popc(g_bits[w] & ((1u << bit) - 1u));
    g_inv[i] = (int)rank;
    atomicAdd(&g_cnt[rank], 1);
    atomicAdd(&g_sums[rank * 3 + 0], pts[i * 5 + 1]);
    atomicAdd(&g_sums[rank * 3 + 1], pts[i * 5 + 2]);
    atomicAdd(&g_sums[rank * 3 + 2], pts[i * 5 + 3]);
}

__global__ void k_zero(float* __restrict__ out, float* __restrict__ oc,
                       int emit_coords) {
    int i = blockIdx.x * 256 + threadIdx.x;
    if (i >= NP) return;
    int nu = g_nuniq;
    bool tail = i >= nu;
    bool multi = !tail && (g_cnt[i] > 1);
    if (tail || multi) {
        float4* o = (float4*)&out[(size_t)i * 128];
        #pragma unroll
        for (int q = 0; q < 32; q++) o[q] = make_float4(0.f, 0.f, 0.f, 0.f);
    }
    if (multi) {
        uint4* xm = (uint4*)&g_xmaxu[(size_t)i * 64];
        #pragma unroll
        for (int q = 0; q < 16; q++) xm[q] = make_uint4(0u, 0u, 0u, 0u);
    }
    if (tail && emit_coords)
        ((float4*)oc)[i] = make_float4(-1.f, 19.f, 799.f, 703.f);
}

__global__ void k_coords(float* __restrict__ oc) {
    int w = blockIdx.x * 256 + threadIdx.x;
    if (w >= NWORDS) return;
    unsigned m = g_bits[w];
    if (!m) return;
    unsigned r = g_boff[w >> 10] + g_wpre[w];
    int kb = w << 5;
    while (m) {
        int b = __ffs(m) - 1;
        m &= m - 1;
        int key = kb + b;
        int B = key / SXYZ;
        int rem = key % SXYZ;
        int X = rem / SYZ; rem -= X * SYZ;
        int Y = rem / SZ;
        int Z = rem - Y * SZ;
        ((float4*)oc)[r] = make_float4((float)B, (float)Z, (float)Y, (float)X);
        r++;
    }
}

__global__ void k_wsum(const float* __restrict__ W1) {
    int j = blockIdx.x * 256 + threadIdx.x;
    if (j < 8192) g_wsum[j] = W1[j] + W1[j + 8192];
}

__global__ void __launch_bounds__(256) k_prep(const float* __restrict__ pts,
                                              const float* __restrict__ W0) {
    __shared__ float w0s[640];
    __shared__ float sm[65];
    int tid = threadIdx.x;
    for (int j = tid; j < 640; j += 256) w0s[j] = W0[j];
    if (tid < 65) sm[tid] = 0.f;
    __syncthreads();
    float mom[65];
    #pragma unroll
    for (int v = 0; v < 65; v++) mom[v] = 0.f;
    int base = blockIdx.x * 2048;
    for (int i = base + tid; i < base + 2048 && i < NP; i += 256) {
        float f[10];
        int seg, cnt;
        compute_feat(pts, i, f, seg, cnt);
        #pragma unroll
        for (int k = 0; k < 10; k++) mom[k] += f[k];
        {
            int idx = 10;
            #pragma unroll
            for (int k = 0; k < 10; k++)
                #pragma unroll
                for (int l = k; l < 10; l++)
                    mom[idx++] += f[k] * f[l];
        }
        if (cnt > 1) {
            int mi = atomicAdd(&g_nmulti, 1);
            g_mlist[mi] = i;
            unsigned* xm = &g_xmaxu[(size_t)seg * 64];
            #pragma unroll 8
            for (int c = 0; c < 64; c++) {
                float acc = 0.f;
                #pragma unroll
                for (int k = 0; k < 10; k++) acc = fmaf(f[k], w0s[k * 64 + c], acc);
                atomicMax(&xm[c], utrans(acc));
            }
        }
    }
    int lane = tid & 31;
    #pragma unroll
    for (int v = 0; v < 65; v++) {
        float s = mom[v];
        #pragma unroll
        for (int o = 16; o; o >>= 1) s += __shfl_down_sync(0xffffffffu, s, o);
        if (lane == 0) atomicAdd(&sm[v], s);
    }
    __syncthreads();
    if (tid < 65) atomicAdd(&g_mom[tid], (double)sm[tid]);
}

__global__ void k_bn0(const float* __restrict__ W0,
                      const float* __restrict__ g, const float* __restrict__ b) {
    int c = threadIdx.x;
    if (c >= 64) return;
    double w[10];
    #pragma unroll
    for (int k = 0; k < 10; k++) w[k] = (double)W0[k * 64 + c];
    double mean = 0.0;
    #pragma unroll
    for (int k = 0; k < 10; k++) mean += w[k] * g_mom[k];
    mean /= (double)NP;
    double ey2 = 0.0;
    int idx = 10;
    #pragma unroll
    for (int k = 0; k < 10; k++)
        #pragma unroll
        for (int l = k; l < 10; l++) {
            double t = w[k] * w[l] * g_mom[idx++];
            ey2 += (k == l) ? t : 2.0 * t;
        }
    ey2 /= (double)NP;
    double var = ey2 - mean * mean;
    double s = (double)g[c] / sqrt(var + 0.001);
    g_s0[c] = (float)s;
    g_t0[c] = (float)((double)b[c] - mean * s);
}

/* shared xs fill: h0 = relu(bn0(f @ W0)), [k][m] stride 132 */
__device__ __forceinline__ void fill_xs(const float* __restrict__ pts,
                                        const float* __restrict__ w0s,
                                        const float* __restrict__ sS,
                                        const float* __restrict__ sT,
                                        float* xs, int bs, int tid) {
    int m = tid & 127, half = tid >> 7;
    float f[10];
    int seg, cnt;
    compute_feat(pts, bs + m, f, seg, cnt);
    int cbase = half * 32;
    #pragma unroll 8
    for (int c = cbase; c < cbase + 32; c++) {
        float acc = 0.f;
        #pragma unroll
        for (int k = 0; k < 10; k++) acc = fmaf(f[k], w0s[k * 64 + c], acc);
        xs[c * 132 + m] = fmaxf(fmaf(acc, sS[c], sT[c]), 0.f);
    }
}

/* shared fma2 core: acc[8][4] (8 rows x 8 cols packed) */
__device__ __forceinline__ void gemm_core(const float* xs, const float* ws,
                                          int tx, int ty,
                                          unsigned long long acc[8][4]) {
    #pragma unroll 2
    for (int k = 0; k < 64; k++) {
        float4 a0 = *(const float4*)&xs[k * 132 + ty * 8];
        float4 a1 = *(const float4*)&xs[k * 132 + ty * 8 + 4];
        unsigned long long am[8];
        am[0] = pk2(a0.x, a0.x); am[1] = pk2(a0.y, a0.y);
        am[2] = pk2(a0.z, a0.z); am[3] = pk2(a0.w, a0.w);
        am[4] = pk2(a1.x, a1.x); am[5] = pk2(a1.y, a1.y);
        am[6] = pk2(a1.z, a1.z); am[7] = pk2(a1.w, a1.w);
        ulonglong2 b0 = *(const ulonglong2*)&ws[k * 128 + tx * 8];
        ulonglong2 b1 = *(const ulonglong2*)&ws[k * 128 + tx * 8 + 4];
        #pragma unroll
        for (int i = 0; i < 8; i++) {
            acc[i][0] = fma2(am[i], b0.x, acc[i][0]);
            acc[i][1] = fma2(am[i], b0.y, acc[i][1]);
            acc[i][2] = fma2(am[i], b1.x, acc[i][2]);
            acc[i][3] = fma2(am[i], b1.y, acc[i][3]);
        }
    }
}

/* Pass 1: BN1 stats only (no y1 materialization) */
__global__ void __launch_bounds__(256, 2) k_gemm_stats(const float* __restrict__ pts,
                                                       const float* __restrict__ W0) {
    extern __shared__ float sh[];
    float* ws = sh;            /* 64*128 */
    float* xs = sh + 8192;     /* 64*132 */
    __shared__ float w0s[640];
    __shared__ float sS[64], sT[64];
    int tid = threadIdx.x;
    if (tid < 64)  { sS[tid] = g_s0[tid]; sT[tid] = g_t0[tid]; }
    for (int j = tid; j < 640; j += 256) w0s[j] = W0[j];
    {
        const float4* w4 = (const float4*)g_wsum;
        float4* ws4 = (float4*)ws;
        for (int j = tid; j < 2048; j += 256) ws4[j] = w4[j];
    }
    __syncthreads();
    int bs = blockIdx.x * 128;
    fill_xs(pts, w0s, sS, sT, xs, bs, tid);
    __syncthreads();

    int tx = tid & 15, ty = tid >> 4;
    unsigned long long acc[8][4];
    #pragma unroll
    for (int i = 0; i < 8; i++)
        #pragma unroll
        for (int p = 0; p < 4; p++) acc[i][p] = 0ull;
    gemm_core(xs, ws, tx, ty, acc);

    float cs[8] = {0,0,0,0,0,0,0,0}, cs2[8] = {0,0,0,0,0,0,0,0};
    #pragma unroll
    for (int i = 0; i < 8; i++) {
        float v[8];
        #pragma unroll
        for (int p = 0; p < 4; p++) upk(acc[i][p], v[2 * p], v[2 * p + 1]);
        #pragma unroll
        for (int j = 0; j < 8; j++) { cs[j] += v[j]; cs2[j] += v[j] * v[j]; }
    }
    __syncthreads();
    #pragma unroll
    for (int j = 0; j < 8; j++) xs[ty * 128 + tx * 8 + j] = cs[j];
    __syncthreads();
    if (tid < 128) {
        float s = 0.f;
        #pragma unroll
        for (int r = 0; r < 16; r++) s += xs[r * 128 + tid];
        atomicAdd(&g_st[128 + tid], (double)s);
    }
    __syncthreads();
    #pragma unroll
    for (int j = 0; j < 8; j++) xs[ty * 128 + tx * 8 + j] = cs2[j];
    __syncthreads();
    if (tid < 128) {
        float s = 0.f;
        #pragma unroll
        for (int r = 0; r < 16; r++) s += xs[r * 128 + tid];
        atomicAdd(&g_st[256 + tid], (double)s);
    }
}

/* multi-row correction: corr = (hmax - h0) @ W1b + exact stat deltas */
__global__ void k_corr(const float* __restrict__ pts,
                       const float* __restrict__ W0,
                       const float* __restrict__ W1) {
    __shared__ float w0s[640];
    __shared__ float hv[64], dv[64];
    int tid = threadIdx.x;   /* 128 */
    for (int j = tid; j < 640; j += 128) w0s[j] = W0[j];
    __syncthreads();
    double dsum = 0.0, dsq = 0.0;
    int nm = g_nmulti;
    for (int it = blockIdx.x; it < nm; it += gridDim.x) {
        int p = g_mlist[it];
        float f[10];
        int seg, cnt;
        compute_feat(pts, p, f, seg, cnt);
        if (tid < 64) {
            float acc = 0.f;
            #pragma unroll
            for (int k = 0; k < 10; k++) acc = fmaf(f[k], w0s[k * 64 + tid], acc);
            float h0 = fmaxf(fmaf(acc, g_s0[tid], g_t0[tid]), 0.f);
            float hm = fmaxf(fmaf(uinv(g_xmaxu[(size_t)seg * 64 + tid]),
                                  g_s0[tid], g_t0[tid]), 0.f);
            hv[tid] = h0;
            dv[tid] = hm - h0;
        }
        __syncthreads();
        float ya = 0.f, co = 0.f;
        #pragma unroll 8
        for (int k = 0; k < 64; k++) ya = fmaf(hv[k], g_wsum[k * 128 + tid], ya);
        #pragma unroll 8
        for (int k = 0; k < 64; k++) co = fmaf(dv[k], W1[(64 + k) * 128 + tid], co);
        g_corr[(size_t)p * 128 + tid] = co;
        float nw = ya + co;
        dsum += (double)co;
        dsq  += (double)nw * (double)nw - (double)ya * (double)ya;
        __syncthreads();
    }
    atomicAdd(&g_st[128 + tid], dsum);
    atomicAdd(&g_st[256 + tid], dsq);
}

__global__ void k_bn1(const float* __restrict__ g, const float* __restrict__ b) {
    int c = threadIdx.x;
    if (c >= 128) return;
    double m = g_st[128 + c] / (double)NP;
    double var = g_st[256 + c] / (double)NP - m * m;
    double s = (double)g[c] / sqrt(var + 0.001);
    g_s1[c] = (float)s;
    g_t1[c] = (float)((double)b[c] - m * s);
}

/* Pass 2: recompute GEMM + corr + BN1 + relu + segment-max -> out */
__global__ void __launch_bounds__(256, 2) k_gemm_out(const float* __restrict__ pts,
                                                     const float* __restrict__ W0,
                                                     float* __restrict__ out) {
    extern __shared__ float sh[];
    float* ws = sh;
    float* xs = sh + 8192;
    __shared__ float w0s[640];
    __shared__ float sS[64], sT[64];
    __shared__ float ss1[128], st1[128];
    int tid = threadIdx.x;
    if (tid < 64)  { sS[tid] = g_s0[tid]; sT[tid] = g_t0[tid]; }
    if (tid < 128) { ss1[tid] = g_s1[tid]; st1[tid] = g_t1[tid]; }
    for (int j = tid; j < 640; j += 256) w0s[j] = W0[j];
    {
        const float4* w4 = (const float4*)g_wsum;
        float4* ws4 = (float4*)ws;
        for (int j = tid; j < 2048; j += 256) ws4[j] = w4[j];
    }
    __syncthreads();
    int bs = blockIdx.x * 128;
    fill_xs(pts, w0s, sS, sT, xs, bs, tid);
    __syncthreads();

    int tx = tid & 15, ty = tid >> 4;
    unsigned long long acc[8][4];
    #pragma unroll
    for (int i = 0; i < 8; i++)
        #pragma unroll
        for (int p = 0; p < 4; p++) acc[i][p] = 0ull;
    gemm_core(xs, ws, tx, ty, acc);

    #pragma unroll
    for (int i = 0; i < 8; i++) {
        float v[8];
        #pragma unroll
        for (int p = 0; p < 4; p++) upk(acc[i][p], v[2 * p], v[2 * p + 1]);
        int pt = bs + ty * 8 + i;
        int seg = g_inv[pt];
        int cnt = g_cnt[seg];
        if (cnt > 1) {
            const float4* cr = (const float4*)&g_corr[(size_t)pt * 128 + tx * 8];
            float4 c0 = cr[0], c1 = cr[1];
            v[0] += c0.x; v[1] += c0.y; v[2] += c0.z; v[3] += c0.w;
            v[4] += c1.x; v[5] += c1.y; v[6] += c1.z; v[7] += c1.w;
        }
        float h[8];
        #pragma unroll
        for (int j = 0; j < 8; j++)
            h[j] = fmaxf(fmaf(v[j], ss1[tx * 8 + j], st1[tx * 8 + j]), 0.f);
        if (cnt == 1) {
            float4* dst = (float4*)&out[(size_t)seg * 128 + tx * 8];
            dst[0] = make_float4(h[0], h[1], h[2], h[3]);
            dst[1] = make_float4(h[4], h[5], h[6], h[7]);
        } else {
            int* ob = (int*)&out[(size_t)seg * 128 + tx * 8];
            #pragma unroll
            for (int j = 0; j < 8; j++)
                atomicMax(&ob[j], __float_as_int(h[j]));
        }
    }
}

extern "C" void kernel_launch(void* const* d_in, const int* in_sizes, int n_in,
                              void* d_out, int out_size) {
    const float* pts = (const float*)d_in[0];
    const float* W0  = (const float*)d_in[1];
    const float* g0  = (const float*)d_in[2];
    const float* b0  = (const float*)d_in[3];
    const float* W1  = (const float*)d_in[4];
    const float* g1  = (const float*)d_in[5];
    const float* b1  = (const float*)d_in[6];
    float* out = (float*)d_out;
    float* oc = out + (size_t)NP * 128;
    int emit_coords = ((long long)out_size >= (long long)NP * 132);

    void *p_bits, *p_cnt, *p_sums, *p_st, *p_nm, *p_mom;
    cudaGetSymbolAddress(&p_bits, g_bits);
    cudaGetSymbolAddress(&p_cnt,  g_cnt);
    cudaGetSymbolAddress(&p_sums, g_sums);
    cudaGetSymbolAddress(&p_st,   g_st);
    cudaGetSymbolAddress(&p_nm,   g_nmulti);
    cudaGetSymbolAddress(&p_mom,  g_mom);

    cudaMemsetAsync(p_bits, 0, NWORDS * 4);
    cudaMemsetAsync(p_cnt,  0, NP * 4);
    cudaMemsetAsync(p_sums, 0, NP * 12);
    cudaMemsetAsync(p_st,   0, 384 * 8);
    cudaMemsetAsync(p_nm,   0, 4);
    cudaMemsetAsync(p_mom,  0, 65 * 8);

    k_keys<<<1563, 256>>>(pts);
    k_scan_words<<<SCAN_BLOCKS, 256>>>();
    k_scan_blocks<<<1, 1024>>>();
    k_inv<<<1563, 256>>>(pts);
    k_zero<<<1563, 256>>>(out, oc, emit_coords);
    if (emit_coords) {
        k_coords<<<2750, 256>>>(oc);
    }
    k_wsum<<<32, 256>>>(W1);
    k_prep<<<196, 256>>>(pts, W0);
    k_bn0<<<1, 64>>>(W0, g0, b0);
    cudaFuncSetAttribute(k_gemm_stats, cudaFuncAttributeMaxDynamicSharedMemorySize, 66560);
    cudaFuncSetAttribute(k_gemm_out,   cudaFuncAttributeMaxDynamicSharedMemorySize, 66560);
    k_gemm_stats<<<3125, 256, 66560>>>(pts, W0);
    k_corr<<<592, 128>>>(pts, W0, W1);
    k_bn1<<<1, 128>>>(g1, b1);
    k_gemm_out<<<3125, 256, 66560>>>(pts, W0, out);
}

// round 17
// speedup vs baseline: 1.9731x; 1.3253x over previous
#include <cuda_runtime.h>
#include <cuda_fp16.h>

#define NP 400000
#define SXYZ 11264000
#define SYZ 16000
#define SZ 20
#define NWORDS 704000
#define SCAN_BLOCKS 688

#define OFF0 (0.05f)
#define OFF1 (0.05f - 40.0f)
#define OFF2 (0.1f - 3.0f)

__device__ unsigned g_bits[NWORDS];
__device__ unsigned g_wpre[NWORDS];
__device__ unsigned g_bsum[SCAN_BLOCKS];
__device__ unsigned g_boff[SCAN_BLOCKS];
__device__ int      g_nuniq;
__device__ int      g_nmulti;
__device__ int      g_mlist[NP];
__device__ int      g_keys[NP];
__device__ int      g_inv[NP];
__device__ int      g_cnt[NP];
__device__ float    g_sums[NP * 3];
__device__ unsigned g_xmaxu[(size_t)NP * 64];   /* only multi segs used */
__device__ unsigned g_y1h[(size_t)NP * 64];     /* y1 as packed half2 */
__device__ float    g_wsum[8192];               /* W1a + W1b */
__device__ double   g_mom[65];                  /* Sf[10], Sff[55] */
__device__ double   g_st[384];                  /* [128:256) sum1, [256:384) sumsq1 */
__device__ float    g_s0[64], g_t0[64], g_s1[128], g_t1[128];

__device__ __forceinline__ void coords_of(float x, float y, float z,
                                          int& cx, int& cy, int& cz) {
    cx = (int)floorf(__fmul_rn(x, 10.0f));
    cy = (int)floorf(__fmul_rn(__fadd_rn(y, 40.0f), 10.0f));
    cz = (int)floorf(__fmul_rn(__fadd_rn(z, 3.0f), 5.0f));
}
__device__ __forceinline__ unsigned utrans(float x) {
    unsigned u = __float_as_uint(x);
    return (u & 0x80000000u) ? ~u : (u | 0x80000000u);
}
__device__ __forceinline__ float uinv(unsigned u) {
    return __uint_as_float((u & 0x80000000u) ? (u & 0x7fffffffu) : ~u);
}
__device__ __forceinline__ unsigned long long pk2(float a, float b) {
    unsigned long long r;
    asm("mov.b64 %0,{%1,%2};" : "=l"(r) : "f"(a), "f"(b));
    return r;
}
__device__ __forceinline__ void upk(unsigned long long v, float& a, float& b) {
    asm("mov.b64 {%0,%1},%2;" : "=f"(a), "=f"(b) : "l"(v));
}
__device__ __forceinline__ unsigned long long fma2(unsigned long long a,
                                                   unsigned long long b,
                                                   unsigned long long c) {
    unsigned long long d;
    asm("fma.rn.f32x2 %0,%1,%2,%3;" : "=l"(d) : "l"(a), "l"(b), "l"(c));
    return d;
}

__device__ __forceinline__ void compute_feat(const float* __restrict__ pts,
                                             int i, float* f,
                                             int& seg, int& cnt) {
    float x = pts[i * 5 + 1], y = pts[i * 5 + 2], z = pts[i * 5 + 3];
    float inten = pts[i * 5 + 4];
    int cx, cy, cz;
    coords_of(x, y, z, cx, cy, cz);
    seg = g_inv[i];
    cnt = g_cnt[seg];
    float fc = fmaxf((float)cnt, 1.f);
    f[0] = x; f[1] = y; f[2] = z; f[3] = inten;
    f[4] = __fsub_rn(x, __fdiv_rn(g_sums[seg * 3 + 0], fc));
    f[5] = __fsub_rn(y, __fdiv_rn(g_sums[seg * 3 + 1], fc));
    f[6] = __fsub_rn(z, __fdiv_rn(g_sums[seg * 3 + 2], fc));
    f[7] = __fsub_rn(x, __fadd_rn(__fmul_rn((float)cx, 0.1f), OFF0));
    f[8] = __fsub_rn(y, __fadd_rn(__fmul_rn((float)cy, 0.1f), OFF1));
    f[9] = __fsub_rn(z, __fadd_rn(__fmul_rn((float)cz, 0.2f), OFF2));
}

__global__ void k_keys(const float* __restrict__ pts) {
    int i = blockIdx.x * 256 + threadIdx.x;
    if (i >= NP) return;
    float b = pts[i * 5 + 0];
    float x = pts[i * 5 + 1], y = pts[i * 5 + 2], z = pts[i * 5 + 3];
    int cx, cy, cz;
    coords_of(x, y, z, cx, cy, cz);
    int key = (int)b * SXYZ + cx * SYZ + cy * SZ + cz;
    g_keys[i] = key;
    atomicOr(&g_bits[(unsigned)key >> 5], 1u << (key & 31));
}

__global__ void k_scan_words() {
    __shared__ unsigned sh[256];
    unsigned b = blockIdx.x, t = threadIdx.x;
    unsigned base = b * 1024u + t * 4u;
    uint4 w = make_uint4(0u, 0u, 0u, 0u);
    if (base < NWORDS) w = *(const uint4*)&g_bits[base];
    unsigned c0 = __popc(w.x), c1 = __popc(w.y), c2 = __popc(w.z), c3 = __popc(w.w);
    unsigned tot = c0 + c1 + c2 + c3;
    sh[t] = tot;
    __syncthreads();
    for (int off = 1; off < 256; off <<= 1) {
        unsigned v = (t >= (unsigned)off) ? sh[t - off] : 0u;
        __syncthreads();
        sh[t] += v;
        __syncthreads();
    }
    unsigned excl = sh[t] - tot;
    if (base < NWORDS) {
        g_wpre[base + 0] = excl;
        g_wpre[base + 1] = excl + c0;
        g_wpre[base + 2] = excl + c0 + c1;
        g_wpre[base + 3] = excl + c0 + c1 + c2;
    }
    if (t == 255) g_bsum[b] = sh[255];
}

__global__ void k_scan_blocks() {
    __shared__ unsigned sh[1024];
    int t = threadIdx.x;
    unsigned v = (t < SCAN_BLOCKS) ? g_bsum[t] : 0u;
    sh[t] = v;
    __syncthreads();
    for (int off = 1; off < 1024; off <<= 1) {
        unsigned u = (t >= off) ? sh[t - off] : 0u;
        __syncthreads();
        sh[t] += u;
        __syncthreads();
    }
    if (t < SCAN_BLOCKS) g_boff[t] = sh[t] - v;
    if (t == 1023) g_nuniq = (int)sh[1023];
}

__global__ void k_inv(const float* __restrict__ pts) {
    int i = blockIdx.x * 256 + threadIdx.x;
    if (i >= NP) return;
    int key = g_keys[i];
    unsigned w = (unsigned)key >> 5, bit = key & 31;
    unsigned rank = g_boff[w >> 10] + g_wpre[w] +
                    __popc(g_bits[w] & ((1u << bit) - 1u));
    g_inv[i] = (int)rank;
    atomicAdd(&g_cnt[rank], 1);
    atomicAdd(&g_sums[rank * 3 + 0], pts[i * 5 + 1]);
    atomicAdd(&g_sums[rank * 3 + 1], pts[i * 5 + 2]);
    atomicAdd(&g_sums[rank * 3 + 2], pts[i * 5 + 3]);
}

__global__ void k_zero(float* __restrict__ out, float* __restrict__ oc,
                       int emit_coords) {
    int i = blockIdx.x * 256 + threadIdx.x;
    if (i >= NP) return;
    int nu = g_nuniq;
    bool tail = i >= nu;
    bool multi = !tail && (g_cnt[i] > 1);
    if (tail || multi) {
        float4* o = (float4*)&out[(size_t)i * 128];
        #pragma unroll
        for (int q = 0; q < 32; q++) o[q] = make_float4(0.f, 0.f, 0.f, 0.f);
    }
    if (multi) {
        uint4* xm = (uint4*)&g_xmaxu[(size_t)i * 64];
        #pragma unroll
        for (int q = 0; q < 16; q++) xm[q] = make_uint4(0u, 0u, 0u, 0u);
    }
    if (tail && emit_coords)
        ((float4*)oc)[i] = make_float4(-1.f, 19.f, 799.f, 703.f);
}

__global__ void k_coords(float* __restrict__ oc) {
    int w = blockIdx.x * 256 + threadIdx.x;
    if (w >= NWORDS) return;
    unsigned m = g_bits[w];
    if (!m) return;
    unsigned r = g_boff[w >> 10] + g_wpre[w];
    int kb = w << 5;
    while (m) {
        int b = __ffs(m) - 1;
        m &= m - 1;
        int key = kb + b;
        int B = key / SXYZ;
        int rem = key % SXYZ;
        int X = rem / SYZ; rem -= X * SYZ;
        int Y = rem / SZ;
        int Z = rem - Y * SZ;
        ((float4*)oc)[r] = make_float4((float)B, (float)Z, (float)Y, (float)X);
        r++;
    }
}

__global__ void k_wsum(const float* __restrict__ W1) {
    int j = blockIdx.x * 256 + threadIdx.x;
    if (j < 8192) g_wsum[j] = W1[j] + W1[j + 8192];
}

__global__ void __launch_bounds__(256) k_prep(const float* __restrict__ pts,
                                              const float* __restrict__ W0) {
    __shared__ float w0s[640];
    __shared__ float sm[65];
    int tid = threadIdx.x;
    for (int j = tid; j < 640; j += 256) w0s[j] = W0[j];
    if (tid < 65) sm[tid] = 0.f;
    __syncthreads();
    float mom[65];
    #pragma unroll
    for (int v = 0; v < 65; v++) mom[v] = 0.f;
    int base = blockIdx.x * 2048;
    for (int i = base + tid; i < base + 2048 && i < NP; i += 256) {
        float f[10];
        int seg, cnt;
        compute_feat(pts, i, f, seg, cnt);
        #pragma unroll
        for (int k = 0; k < 10; k++) mom[k] += f[k];
        {
            int idx = 10;
            #pragma unroll
            for (int k = 0; k < 10; k++)
                #pragma unroll
                for (int l = k; l < 10; l++)
                    mom[idx++] += f[k] * f[l];
        }
        if (cnt > 1) {
            int mi = atomicAdd(&g_nmulti, 1);
            g_mlist[mi] = i;
            unsigned* xm = &g_xmaxu[(size_t)seg * 64];
            #pragma unroll 8
            for (int c = 0; c < 64; c++) {
                float acc = 0.f;
                #pragma unroll
                for (int k = 0; k < 10; k++) acc = fmaf(f[k], w0s[k * 64 + c], acc);
                atomicMax(&xm[c], utrans(acc));
            }
        }
    }
    int lane = tid & 31;
    #pragma unroll
    for (int v = 0; v < 65; v++) {
        float s = mom[v];
        #pragma unroll
        for (int o = 16; o; o >>= 1) s += __shfl_down_sync(0xffffffffu, s, o);
        if (lane == 0) atomicAdd(&sm[v], s);
    }
    __syncthreads();
    if (tid < 65) atomicAdd(&g_mom[tid], (double)sm[tid]);
}

__global__ void k_bn0(const float* __restrict__ W0,
                      const float* __restrict__ g, const float* __restrict__ b) {
    int c = threadIdx.x;
    if (c >= 64) return;
    double w[10];
    #pragma unroll
    for (int k = 0; k < 10; k++) w[k] = (double)W0[k * 64 + c];
    double mean = 0.0;
    #pragma unroll
    for (int k = 0; k < 10; k++) mean += w[k] * g_mom[k];
    mean /= (double)NP;
    double ey2 = 0.0;
    int idx = 10;
    #pragma unroll
    for (int k = 0; k < 10; k++)
        #pragma unroll
        for (int l = k; l < 10; l++) {
            double t = w[k] * w[l] * g_mom[idx++];
            ey2 += (k == l) ? t : 2.0 * t;
        }
    ey2 /= (double)NP;
    double var = ey2 - mean * mean;
    double s = (double)g[c] / sqrt(var + 0.001);
    g_s0[c] = (float)s;
    g_t0[c] = (float)((double)b[c] - mean * s);
}

/* Pass A: y1 = h0 @ (W1a+W1b), h0 recomputed; y1 stored fp16; exact stats */
__global__ void __launch_bounds__(256, 2) k_gemm1(const float* __restrict__ pts,
                                                  const float* __restrict__ W0) {
    extern __shared__ float sh[];
    float* ws = sh;            /* 64*128 */
    float* xs = sh + 8192;     /* 64*132 */
    __shared__ float w0s[640];
    __shared__ float sS[64], sT[64];
    int tid = threadIdx.x;
    if (tid < 64)  { sS[tid] = g_s0[tid]; sT[tid] = g_t0[tid]; }
    for (int j = tid; j < 640; j += 256) w0s[j] = W0[j];
    {
        const float4* w4 = (const float4*)g_wsum;
        float4* ws4 = (float4*)ws;
        for (int j = tid; j < 2048; j += 256) ws4[j] = w4[j];
    }
    __syncthreads();

    int bs = blockIdx.x * 128;
    {
        int m = tid & 127, half = tid >> 7;
        float f[10];
        int seg, cnt;
        compute_feat(pts, bs + m, f, seg, cnt);
        int cbase = half * 32;
        #pragma unroll 8
        for (int c = cbase; c < cbase + 32; c++) {
            float acc = 0.f;
            #pragma unroll
            for (int k = 0; k < 10; k++) acc = fmaf(f[k], w0s[k * 64 + c], acc);
            xs[c * 132 + m] = fmaxf(fmaf(acc, sS[c], sT[c]), 0.f);
        }
    }
    __syncthreads();

    int tx = tid & 15, ty = tid >> 4;
    unsigned long long acc[8][4];
    #pragma unroll
    for (int i = 0; i < 8; i++)
        #pragma unroll
        for (int p = 0; p < 4; p++) acc[i][p] = 0ull;

    #pragma unroll 2
    for (int k = 0; k < 64; k++) {
        float4 a0 = *(const float4*)&xs[k * 132 + ty * 8];
        float4 a1 = *(const float4*)&xs[k * 132 + ty * 8 + 4];
        unsigned long long am[8];
        am[0] = pk2(a0.x, a0.x); am[1] = pk2(a0.y, a0.y);
        am[2] = pk2(a0.z, a0.z); am[3] = pk2(a0.w, a0.w);
        am[4] = pk2(a1.x, a1.x); am[5] = pk2(a1.y, a1.y);
        am[6] = pk2(a1.z, a1.z); am[7] = pk2(a1.w, a1.w);
        ulonglong2 b0 = *(const ulonglong2*)&ws[k * 128 + tx * 8];
        ulonglong2 b1 = *(const ulonglong2*)&ws[k * 128 + tx * 8 + 4];
        #pragma unroll
        for (int i = 0; i < 8; i++) {
            acc[i][0] = fma2(am[i], b0.x, acc[i][0]);
            acc[i][1] = fma2(am[i], b0.y, acc[i][1]);
            acc[i][2] = fma2(am[i], b1.x, acc[i][2]);
            acc[i][3] = fma2(am[i], b1.y, acc[i][3]);
        }
    }

    float cs[8] = {0,0,0,0,0,0,0,0}, cs2[8] = {0,0,0,0,0,0,0,0};
    #pragma unroll
    for (int i = 0; i < 8; i++) {
        float v[8];
        #pragma unroll
        for (int p = 0; p < 4; p++) upk(acc[i][p], v[2 * p], v[2 * p + 1]);
        int pt = bs + ty * 8 + i;
        __half2 h01 = __floats2half2_rn(v[0], v[1]);
        __half2 h23 = __floats2half2_rn(v[2], v[3]);
        __half2 h45 = __floats2half2_rn(v[4], v[5]);
        __half2 h67 = __floats2half2_rn(v[6], v[7]);
        uint4 st;
        st.x = *(unsigned*)&h01; st.y = *(unsigned*)&h23;
        st.z = *(unsigned*)&h45; st.w = *(unsigned*)&h67;
        *(uint4*)&g_y1h[(size_t)pt * 64 + tx * 4] = st;
        #pragma unroll
        for (int j = 0; j < 8; j++) { cs[j] += v[j]; cs2[j] += v[j] * v[j]; }
    }
    __syncthreads();
    #pragma unroll
    for (int j = 0; j < 8; j++) xs[ty * 128 + tx * 8 + j] = cs[j];
    __syncthreads();
    if (tid < 128) {
        float s = 0.f;
        #pragma unroll
        for (int r = 0; r < 16; r++) s += xs[r * 128 + tid];
        atomicAdd(&g_st[128 + tid], (double)s);
    }
    __syncthreads();
    #pragma unroll
    for (int j = 0; j < 8; j++) xs[ty * 128 + tx * 8 + j] = cs2[j];
    __syncthreads();
    if (tid < 128) {
        float s = 0.f;
        #pragma unroll
        for (int r = 0; r < 16; r++) s += xs[r * 128 + tid];
        atomicAdd(&g_st[256 + tid], (double)s);
    }
}

/* Pass B: multi-seg correction y1 += (hmax - h0) @ W1b (fp16 RMW) */
__global__ void k_gemm1b(const float* __restrict__ pts,
                         const float* __restrict__ W0,
                         const float* __restrict__ W1) {
    __shared__ float w0s[640];
    __shared__ float d[64];
    __shared__ float cv[128];
    int tid = threadIdx.x;   /* 128 */
    for (int j = tid; j < 640; j += 128) w0s[j] = W0[j];
    __syncthreads();
    double ds0 = 0.0, dq0 = 0.0, ds1 = 0.0, dq1 = 0.0;
    int nm = g_nmulti;
    for (int it = blockIdx.x; it < nm; it += gridDim.x) {
        int p = g_mlist[it];
        float f[10];
        int seg, cnt;
        compute_feat(pts, p, f, seg, cnt);
        if (tid < 64) {
            float acc = 0.f;
            #pragma unroll
            for (int k = 0; k < 10; k++) acc = fmaf(f[k], w0s[k * 64 + tid], acc);
            float h0 = fmaxf(fmaf(acc, g_s0[tid], g_t0[tid]), 0.f);
            float hm = fmaxf(fmaf(uinv(g_xmaxu[(size_t)seg * 64 + tid]),
                                  g_s0[tid], g_t0[tid]), 0.f);
            d[tid] = hm - h0;
        }
        __syncthreads();
        float acc = 0.f;
        #pragma unroll 8
        for (int k = 0; k < 64; k++)
            acc = fmaf(d[k], W1[(64 + k) * 128 + tid], acc);
        cv[tid] = acc;
        __syncthreads();
        if (tid < 64) {
            unsigned ho = g_y1h[(size_t)p * 64 + tid];
            float2 o = __half22float2(*(__half2*)&ho);
            float n0 = o.x + cv[2 * tid];
            float n1 = o.y + cv[2 * tid + 1];
            __half2 nh = __floats2half2_rn(n0, n1);
            g_y1h[(size_t)p * 64 + tid] = *(unsigned*)&nh;
            ds0 += (double)cv[2 * tid];
            dq0 += (double)n0 * (double)n0 - (double)o.x * (double)o.x;
            ds1 += (double)cv[2 * tid + 1];
            dq1 += (double)n1 * (double)n1 - (double)o.y * (double)o.y;
        }
        __syncthreads();
    }
    if (tid < 64) {
        atomicAdd(&g_st[128 + 2 * tid],     ds0);
        atomicAdd(&g_st[256 + 2 * tid],     dq0);
        atomicAdd(&g_st[128 + 2 * tid + 1], ds1);
        atomicAdd(&g_st[256 + 2 * tid + 1], dq1);
    }
}

__global__ void k_bn1(const float* __restrict__ g, const float* __restrict__ b) {
    int c = threadIdx.x;
    if (c >= 128) return;
    double m = g_st[128 + c] / (double)NP;
    double var = g_st[256 + c] / (double)NP - m * m;
    double s = (double)g[c] / sqrt(var + 0.001);
    g_s1[c] = (float)s;
    g_t1[c] = (float)((double)b[c] - m * s);
}

__global__ void k_final(float* __restrict__ out) {
    __shared__ float s1[128], t1[128];
    int tid = threadIdx.x;
    if (tid < 128) { s1[tid] = g_s1[tid]; t1[tid] = g_t1[tid]; }
    __syncthreads();
    int warp = tid >> 5, lane = tid & 31;
    int pbase = blockIdx.x * 64 + warp * 8;
    float4 sv = *(const float4*)&s1[lane * 4];
    float4 tv = *(const float4*)&t1[lane * 4];
    #pragma unroll
    for (int pp = 0; pp < 8; pp++) {
        int p = pbase + pp;
        int seg = g_inv[p];
        int cnt = g_cnt[seg];
        uint2 hv = *(const uint2*)&g_y1h[(size_t)p * 64 + lane * 2];
        float2 va = __half22float2(*(__half2*)&hv.x);
        float2 vb = __half22float2(*(__half2*)&hv.y);
        float4 h;
        h.x = fmaxf(fmaf(va.x, sv.x, tv.x), 0.f);
        h.y = fmaxf(fmaf(va.y, sv.y, tv.y), 0.f);
        h.z = fmaxf(fmaf(vb.x, sv.z, tv.z), 0.f);
        h.w = fmaxf(fmaf(vb.y, sv.w, tv.w), 0.f);
        if (cnt == 1) {
            *(float4*)&out[(size_t)seg * 128 + lane * 4] = h;
        } else {
            int* ob = (int*)&out[(size_t)seg * 128 + lane * 4];
            atomicMax(&ob[0], __float_as_int(h.x));
            atomicMax(&ob[1], __float_as_int(h.y));
            atomicMax(&ob[2], __float_as_int(h.z));
            atomicMax(&ob[3], __float_as_int(h.w));
        }
    }
}

extern "C" void kernel_launch(void* const* d_in, const int* in_sizes, int n_in,
                              void* d_out, int out_size) {
    const float* pts = (const float*)d_in[0];
    const float* W0  = (const float*)d_in[1];
    const float* g0  = (const float*)d_in[2];
    const float* b0  = (const float*)d_in[3];
    const float* W1  = (const float*)d_in[4];
    const float* g1  = (const float*)d_in[5];
    const float* b1  = (const float*)d_in[6];
    float* out = (float*)d_out;
    float* oc = out + (size_t)NP * 128;
    int emit_coords = ((long long)out_size >= (long long)NP * 132);

    void *p_bits, *p_cnt, *p_sums, *p_st, *p_nm, *p_mom;
    cudaGetSymbolAddress(&p_bits, g_bits);
    cudaGetSymbolAddress(&p_cnt,  g_cnt);
    cudaGetSymbolAddress(&p_sums, g_sums);
    cudaGetSymbolAddress(&p_st,   g_st);
    cudaGetSymbolAddress(&p_nm,   g_nmulti);
    cudaGetSymbolAddress(&p_mom,  g_mom);

    cudaMemsetAsync(p_bits, 0, NWORDS * 4);
    cudaMemsetAsync(p_cnt,  0, NP * 4);
    cudaMemsetAsync(p_sums, 0, NP * 12);
    cudaMemsetAsync(p_st,   0, 384 * 8);
    cudaMemsetAsync(p_nm,   0, 4);
    cudaMemsetAsync(p_mom,  0, 65 * 8);

    k_keys<<<1563, 256>>>(pts);
    k_scan_words<<<SCAN_BLOCKS, 256>>>();
    k_scan_blocks<<<1, 1024>>>();
    k_inv<<<1563, 256>>>(pts);
    k_zero<<<1563, 256>>>(out, oc, emit_coords);
    if (emit_coords) {
        k_coords<<<2750, 256>>>(oc);
    }
    k_wsum<<<32, 256>>>(W1);
    k_prep<<<196, 256>>>(pts, W0);
    k_bn0<<<1, 64>>>(W0, g0, b0);
    cudaFuncSetAttribute(k_gemm1, cudaFuncAttributeMaxDynamicSharedMemorySize, 66560);
    k_gemm1<<<3125, 256, 66560>>>(pts, W0);
    k_gemm1b<<<592, 128>>>(pts, W0, W1);
    k_bn1<<<1, 128>>>(g1, b1);
    k_final<<<6250, 256>>>(out);
}